// round 2
// baseline (speedup 1.0000x reference)
#include <cuda_runtime.h>
#include <cuda_bf16.h>
#include <math.h>

// Problem constants
#define BATCH 4
#define SEQ_N 4096
#define SEQ_M 256
#define DIM 1024
#define CTX_DIM 768
#define HEADS 16
#define HD 64                       // DIM / HEADS
#define ROWS_X (BATCH * SEQ_N)      // 16384
#define ROWS_C (BATCH * SEQ_M)      // 1024

// Scratch (device globals: allocation-free per harness rules)
__device__ float g_Q[ROWS_X * DIM];   // 64 MB
__device__ float g_K[ROWS_C * DIM];   // 4 MB
__device__ float g_V[ROWS_C * DIM];   // 4 MB
__device__ float g_AT[ROWS_X * DIM];  // 64 MB

// ---------------------------------------------------------------------------
// Generic fp32 GEMM: C[M,N] = A[M,K] @ B[K,N], row-major.
// 128x128 block tile, BK=16, 256 threads, 8x8 per-thread microtile.
// Requires M%128==0, N%128==0, K%16==0 (true for all uses here).
// ---------------------------------------------------------------------------
__global__ void __launch_bounds__(256, 2)
gemm_kernel(const float* __restrict__ A, const float* __restrict__ B,
            float* __restrict__ C, int M, int N, int K)
{
    __shared__ float As[16][132];   // transposed A tile, padded
    __shared__ float Bs[16][128];

    const int t  = threadIdx.x;
    const int tx = t & 15;
    const int ty = t >> 4;
    const int m0 = blockIdx.y * 128;
    const int n0 = blockIdx.x * 128;

    const float* Ab = A + (size_t)m0 * K;
    const float* Bb = B + n0;

    float acc[8][8];
    #pragma unroll
    for (int i = 0; i < 8; i++)
        #pragma unroll
        for (int j = 0; j < 8; j++) acc[i][j] = 0.0f;

    for (int kt = 0; kt < K; kt += 16) {
        // Load A tile 128x16 (store transposed)
        #pragma unroll
        for (int i = 0; i < 2; i++) {
            int lin = t + i * 256;             // < 512
            int r   = lin >> 2;                // 0..127
            int c4  = (lin & 3) * 4;           // 0,4,8,12
            float4 f = *(const float4*)(Ab + (size_t)r * K + kt + c4);
            As[c4 + 0][r] = f.x;
            As[c4 + 1][r] = f.y;
            As[c4 + 2][r] = f.z;
            As[c4 + 3][r] = f.w;
        }
        // Load B tile 16x128
        #pragma unroll
        for (int i = 0; i < 2; i++) {
            int lin = t + i * 256;             // < 512
            int r   = lin >> 5;                // 0..15
            int c4  = (lin & 31) * 4;          // 0..124
            *(float4*)&Bs[r][c4] = *(const float4*)(Bb + (size_t)(kt + r) * N + c4);
        }
        __syncthreads();

        #pragma unroll
        for (int k = 0; k < 16; k++) {
            float4 a0 = *(const float4*)&As[k][ty * 8];
            float4 a1 = *(const float4*)&As[k][ty * 8 + 4];
            float4 b0 = *(const float4*)&Bs[k][tx * 8];
            float4 b1 = *(const float4*)&Bs[k][tx * 8 + 4];
            float av[8] = {a0.x, a0.y, a0.z, a0.w, a1.x, a1.y, a1.z, a1.w};
            float bv[8] = {b0.x, b0.y, b0.z, b0.w, b1.x, b1.y, b1.z, b1.w};
            #pragma unroll
            for (int i = 0; i < 8; i++)
                #pragma unroll
                for (int j = 0; j < 8; j++)
                    acc[i][j] = fmaf(av[i], bv[j], acc[i][j]);
        }
        __syncthreads();
    }

    float* Cb = C + (size_t)m0 * N + n0;
    #pragma unroll
    for (int i = 0; i < 8; i++) {
        float4 c0 = make_float4(acc[i][0], acc[i][1], acc[i][2], acc[i][3]);
        float4 c1 = make_float4(acc[i][4], acc[i][5], acc[i][6], acc[i][7]);
        *(float4*)(Cb + (size_t)(ty * 8 + i) * N + tx * 8)     = c0;
        *(float4*)(Cb + (size_t)(ty * 8 + i) * N + tx * 8 + 4) = c1;
    }
}

// ---------------------------------------------------------------------------
// Fused attention per (b, h): 64 Q-rows per block, full M=256 keys in smem.
// S = Q K^T * scale (masked) -> softmax rows -> O = P V.
// grid: (SEQ_N/64, BATCH*HEADS), 256 threads.
// Mask arrives as int32 (harness converts bool -> int32).
// ---------------------------------------------------------------------------
#define QS_LD 65
#define KT_LD 260
#define SS_LD 257

__global__ void __launch_bounds__(256, 1)
attn_kernel(const float* __restrict__ Q, const float* __restrict__ Kg,
            const float* __restrict__ Vg, const int* __restrict__ maskp,
            float* __restrict__ O)
{
    extern __shared__ float sm[];
    float* Qs = sm;                      // [64][65]
    float* Kt = Qs + 64 * QS_LD;         // [64][260]  (K transposed: Kt[k][j])
    float* Ss = Kt + 64 * KT_LD;         // [64][257]
    float* Vs = Ss + 64 * SS_LD;         // [256][64]
    int*   Ms = (int*)(Vs + 256 * 64);   // [256]

    const int t  = threadIdx.x;
    const int b  = blockIdx.y >> 4;
    const int h  = blockIdx.y & 15;
    const int n0 = blockIdx.x * 64;

    const float* Qbase = Q  + ((size_t)(b * SEQ_N + n0) * DIM) + h * HD;
    const float* Kbase = Kg + ((size_t)(b * SEQ_M) * DIM) + h * HD;
    const float* Vbase = Vg + ((size_t)(b * SEQ_M) * DIM) + h * HD;

    // Load Q tile 64x64
    #pragma unroll
    for (int i = 0; i < 4; i++) {
        int lin = t + i * 256;            // < 1024
        int r   = lin >> 4;               // 0..63
        int c4  = lin & 15;               // 0..15
        float4 f = *(const float4*)(Qbase + (size_t)r * DIM + c4 * 4);
        float* dst = &Qs[r * QS_LD + c4 * 4];
        dst[0] = f.x; dst[1] = f.y; dst[2] = f.z; dst[3] = f.w;
    }
    // Load K (transposed) and V tiles: 256x64 each
    #pragma unroll
    for (int i = 0; i < 16; i++) {
        int lin = t + i * 256;            // < 4096
        int j   = lin >> 4;               // 0..255
        int c4  = lin & 15;               // 0..15
        float4 f = *(const float4*)(Kbase + (size_t)j * DIM + c4 * 4);
        int k = c4 * 4;
        Kt[(k + 0) * KT_LD + j] = f.x;
        Kt[(k + 1) * KT_LD + j] = f.y;
        Kt[(k + 2) * KT_LD + j] = f.z;
        Kt[(k + 3) * KT_LD + j] = f.w;
        float4 g = *(const float4*)(Vbase + (size_t)j * DIM + c4 * 4);
        *(float4*)&Vs[j * 64 + c4 * 4] = g;
    }
    Ms[t] = maskp[b * SEQ_M + t];   // int32 mask element
    __syncthreads();

    // --- Phase 1: S[64][256] = Q @ K^T -------------------------------------
    const int tc = t & 15;     // 16 col-groups of 16
    const int tr = t >> 4;     // 16 row-groups of 4
    float s[4][16];
    #pragma unroll
    for (int i = 0; i < 4; i++)
        #pragma unroll
        for (int u = 0; u < 16; u++) s[i][u] = 0.0f;

    #pragma unroll 4
    for (int k = 0; k < 64; k++) {
        float a0 = Qs[(tr * 4 + 0) * QS_LD + k];
        float a1 = Qs[(tr * 4 + 1) * QS_LD + k];
        float a2 = Qs[(tr * 4 + 2) * QS_LD + k];
        float a3 = Qs[(tr * 4 + 3) * QS_LD + k];
        const float* bp = &Kt[k * KT_LD + tc * 16];
        float4 b0 = *(const float4*)(bp);
        float4 b1 = *(const float4*)(bp + 4);
        float4 b2 = *(const float4*)(bp + 8);
        float4 b3 = *(const float4*)(bp + 12);
        float bv[16] = {b0.x, b0.y, b0.z, b0.w, b1.x, b1.y, b1.z, b1.w,
                        b2.x, b2.y, b2.z, b2.w, b3.x, b3.y, b3.z, b3.w};
        #pragma unroll
        for (int u = 0; u < 16; u++) {
            s[0][u] = fmaf(a0, bv[u], s[0][u]);
            s[1][u] = fmaf(a1, bv[u], s[1][u]);
            s[2][u] = fmaf(a2, bv[u], s[2][u]);
            s[3][u] = fmaf(a3, bv[u], s[3][u]);
        }
    }

    const float scale = 0.125f;  // hd^-0.5 = 64^-0.5
    #pragma unroll
    for (int i = 0; i < 4; i++) {
        int r = tr * 4 + i;
        #pragma unroll
        for (int u = 0; u < 16; u++) {
            int j = tc * 16 + u;
            Ss[r * SS_LD + j] = Ms[j] ? s[i][u] * scale : -1e30f;
        }
    }
    __syncthreads();

    // --- Phase 2: rowwise softmax ------------------------------------------
    const int warp = t >> 5, lane = t & 31;
    #pragma unroll
    for (int q = 0; q < 8; q++) {
        int r = warp * 8 + q;
        float v[8];
        float m = -INFINITY;
        #pragma unroll
        for (int i = 0; i < 8; i++) {
            v[i] = Ss[r * SS_LD + lane + 32 * i];
            m = fmaxf(m, v[i]);
        }
        #pragma unroll
        for (int off = 16; off >= 1; off >>= 1)
            m = fmaxf(m, __shfl_xor_sync(0xffffffffu, m, off));
        float sum = 0.0f;
        #pragma unroll
        for (int i = 0; i < 8; i++) {
            v[i] = __expf(v[i] - m);
            sum += v[i];
        }
        #pragma unroll
        for (int off = 16; off >= 1; off >>= 1)
            sum += __shfl_xor_sync(0xffffffffu, sum, off);
        float inv = 1.0f / sum;
        #pragma unroll
        for (int i = 0; i < 8; i++)
            Ss[r * SS_LD + lane + 32 * i] = v[i] * inv;
    }
    __syncthreads();

    // --- Phase 3: O[64][64] = P @ V ----------------------------------------
    float o[4][4];
    #pragma unroll
    for (int i = 0; i < 4; i++)
        #pragma unroll
        for (int u = 0; u < 4; u++) o[i][u] = 0.0f;

    #pragma unroll 8
    for (int j = 0; j < 256; j++) {
        float a0 = Ss[(tr * 4 + 0) * SS_LD + j];
        float a1 = Ss[(tr * 4 + 1) * SS_LD + j];
        float a2 = Ss[(tr * 4 + 2) * SS_LD + j];
        float a3 = Ss[(tr * 4 + 3) * SS_LD + j];
        float4 bv = *(const float4*)&Vs[j * 64 + tc * 4];
        o[0][0] = fmaf(a0, bv.x, o[0][0]); o[0][1] = fmaf(a0, bv.y, o[0][1]);
        o[0][2] = fmaf(a0, bv.z, o[0][2]); o[0][3] = fmaf(a0, bv.w, o[0][3]);
        o[1][0] = fmaf(a1, bv.x, o[1][0]); o[1][1] = fmaf(a1, bv.y, o[1][1]);
        o[1][2] = fmaf(a1, bv.z, o[1][2]); o[1][3] = fmaf(a1, bv.w, o[1][3]);
        o[2][0] = fmaf(a2, bv.x, o[2][0]); o[2][1] = fmaf(a2, bv.y, o[2][1]);
        o[2][2] = fmaf(a2, bv.z, o[2][2]); o[2][3] = fmaf(a2, bv.w, o[2][3]);
        o[3][0] = fmaf(a3, bv.x, o[3][0]); o[3][1] = fmaf(a3, bv.y, o[3][1]);
        o[3][2] = fmaf(a3, bv.z, o[3][2]); o[3][3] = fmaf(a3, bv.w, o[3][3]);
    }

    float* Ob = O + ((size_t)(b * SEQ_N + n0) * DIM) + h * HD;
    #pragma unroll
    for (int i = 0; i < 4; i++) {
        *(float4*)(Ob + (size_t)(tr * 4 + i) * DIM + tc * 4) =
            make_float4(o[i][0], o[i][1], o[i][2], o[i][3]);
    }
}

// ---------------------------------------------------------------------------
// Host launcher
// ---------------------------------------------------------------------------
extern "C" void kernel_launch(void* const* d_in, const int* in_sizes, int n_in,
                              void* d_out, int out_size)
{
    const float* x    = (const float*)d_in[0];
    const float* ctx  = (const float*)d_in[1];
    const int*   mask = (const int*)d_in[2];
    const float* Wq   = (const float*)d_in[3];
    const float* Wk   = (const float*)d_in[4];
    const float* Wv   = (const float*)d_in[5];
    const float* Wo   = (const float*)d_in[6];
    float*       out  = (float*)d_out;

    float *Qg, *Kg, *Vg, *ATg;
    cudaGetSymbolAddress((void**)&Qg,  g_Q);
    cudaGetSymbolAddress((void**)&Kg,  g_K);
    cudaGetSymbolAddress((void**)&Vg,  g_V);
    cudaGetSymbolAddress((void**)&ATg, g_AT);

    dim3 blk(256);

    // Projections
    gemm_kernel<<<dim3(DIM / 128, ROWS_X / 128), blk>>>(x,   Wq, Qg, ROWS_X, DIM, DIM);
    gemm_kernel<<<dim3(DIM / 128, ROWS_C / 128), blk>>>(ctx, Wk, Kg, ROWS_C, DIM, CTX_DIM);
    gemm_kernel<<<dim3(DIM / 128, ROWS_C / 128), blk>>>(ctx, Wv, Vg, ROWS_C, DIM, CTX_DIM);

    // Fused attention
    size_t smem_bytes = (size_t)(64 * QS_LD + 64 * KT_LD + 64 * SS_LD + 256 * 64) * sizeof(float) + 1024;
    cudaFuncSetAttribute(attn_kernel, cudaFuncAttributeMaxDynamicSharedMemorySize, (int)smem_bytes);
    attn_kernel<<<dim3(SEQ_N / 64, BATCH * HEADS), blk, smem_bytes>>>(Qg, Kg, Vg, mask, ATg);

    // Output projection
    gemm_kernel<<<dim3(DIM / 128, ROWS_X / 128), blk>>>(ATg, Wo, out, ROWS_X, DIM, DIM);
}

// round 4
// speedup vs baseline: 1.9856x; 1.9856x over previous
#include <cuda_runtime.h>
#include <cuda_bf16.h>
#include <math.h>
#include <stdint.h>

// Problem constants
#define BATCH 4
#define SEQ_N 4096
#define SEQ_M 256
#define DIM 1024
#define CTX_DIM 768
#define HEADS 16
#define HD 64
#define ROWS_X (BATCH * SEQ_N)      // 16384
#define ROWS_C (BATCH * SEQ_M)      // 1024

// Scratch (device globals: allocation-free per harness rules)
__device__ float g_Q[ROWS_X * DIM];
__device__ float g_K[ROWS_C * DIM];
__device__ float g_V[ROWS_C * DIM];
__device__ float g_AT[ROWS_X * DIM];
__device__ __nv_bfloat16 g_Ah[ROWS_X * DIM];
__device__ __nv_bfloat16 g_Al[ROWS_X * DIM];
__device__ __nv_bfloat16 g_Ch[ROWS_C * CTX_DIM];
__device__ __nv_bfloat16 g_Cl[ROWS_C * CTX_DIM];
__device__ __nv_bfloat16 g_Bh[DIM * DIM];
__device__ __nv_bfloat16 g_Bl[DIM * DIM];

// ---------------------------------------------------------------------------
// PTX helpers (portable: sm_80+ features only)
// ---------------------------------------------------------------------------
__device__ __forceinline__ uint32_t smem_u32(const void* p) {
    uint32_t a;
    asm("{ .reg .u64 t; cvta.to.shared.u64 t, %1; cvt.u32.u64 %0, t; }" : "=r"(a) : "l"(p));
    return a;
}
#define CP_ASYNC16(dst, src) \
    asm volatile("cp.async.cg.shared.global [%0], [%1], 16;" :: "r"(dst), "l"(src))
#define CP_COMMIT() asm volatile("cp.async.commit_group;" ::: "memory")
#define CP_WAIT(n)  asm volatile("cp.async.wait_group %0;" :: "n"(n) : "memory")

#define LDM_X4(r0, r1, r2, r3, a) \
    asm volatile("ldmatrix.sync.aligned.m8n8.x4.shared.b16 {%0,%1,%2,%3}, [%4];" \
                 : "=r"(r0), "=r"(r1), "=r"(r2), "=r"(r3) : "r"(a))

#define MMA_BF16(d, a, b) \
    asm volatile("mma.sync.aligned.m16n8k16.row.col.f32.bf16.bf16.f32 " \
                 "{%0,%1,%2,%3},{%4,%5,%6,%7},{%8,%9},{%0,%1,%2,%3};" \
                 : "+f"((d)[0]), "+f"((d)[1]), "+f"((d)[2]), "+f"((d)[3]) \
                 : "r"((a)[0]), "r"((a)[1]), "r"((a)[2]), "r"((a)[3]), \
                   "r"((b)[0]), "r"((b)[1]))

// ---------------------------------------------------------------------------
// fp32 -> bf16 hi/lo split
// ---------------------------------------------------------------------------
__global__ void split_kernel(const float* __restrict__ X, __nv_bfloat16* __restrict__ Xh,
                             __nv_bfloat16* __restrict__ Xl, int n4)
{
    int i = blockIdx.x * blockDim.x + threadIdx.x;
    if (i >= n4) return;
    float4 v = ((const float4*)X)[i];
    float a[4] = {v.x, v.y, v.z, v.w};
    __nv_bfloat16 h[4], l[4];
    #pragma unroll
    for (int j = 0; j < 4; j++) {
        h[j] = __float2bfloat16(a[j]);
        l[j] = __float2bfloat16(a[j] - __bfloat162float(h[j]));
    }
    __nv_bfloat162* Hp = (__nv_bfloat162*)(Xh + 4 * (size_t)i);
    __nv_bfloat162* Lp = (__nv_bfloat162*)(Xl + 4 * (size_t)i);
    Hp[0] = __nv_bfloat162(h[0], h[1]); Hp[1] = __nv_bfloat162(h[2], h[3]);
    Lp[0] = __nv_bfloat162(l[0], l[1]); Lp[1] = __nv_bfloat162(l[2], l[3]);
}

// ---------------------------------------------------------------------------
// W[K][N] -> Th/Tl[N][K] bf16 hi/lo (transpose + split)
// ---------------------------------------------------------------------------
__global__ void transpose_split_kernel(const float* __restrict__ W, __nv_bfloat16* __restrict__ Th,
                                       __nv_bfloat16* __restrict__ Tl, int K, int N)
{
    __shared__ float tile[32][33];
    int n0 = blockIdx.x * 32, k0 = blockIdx.y * 32;
    int tx = threadIdx.x, ty = threadIdx.y;
    #pragma unroll
    for (int j = ty; j < 32; j += 8)
        tile[j][tx] = W[(size_t)(k0 + j) * N + n0 + tx];
    __syncthreads();
    #pragma unroll
    for (int j = ty; j < 32; j += 8) {
        float v = tile[tx][j];
        __nv_bfloat16 h = __float2bfloat16(v);
        __nv_bfloat16 l = __float2bfloat16(v - __bfloat162float(h));
        size_t o = (size_t)(n0 + j) * K + k0 + tx;
        Th[o] = h; Tl[o] = l;
    }
}

// ---------------------------------------------------------------------------
// HMMA bf16-split GEMM: C[M, 1024] = A[M,K] @ W[K,1024]
// A as hi/lo bf16 [M,K]; W pre-transposed+split: Bt[1024][K] hi/lo.
// CTA tile 128x128x32, 8 warps (2x4) of 64x32, cp.async double buffer.
// smem rows padded to 80B (5 granules) -> conflict-free ldmatrix, no swizzle.
// ---------------------------------------------------------------------------
#define BM 128
#define BN 128
#define BK 32
#define PITCH 80
#define TILE_B (128 * PITCH)        // 10240
#define STAGE  (4 * TILE_B)         // 40960
#define GEMM_SMEM (2 * STAGE)       // 81920

__global__ void __launch_bounds__(256, 1)
gemm_hmma_kernel(const __nv_bfloat16* __restrict__ Ah, const __nv_bfloat16* __restrict__ Al,
                 const __nv_bfloat16* __restrict__ Bh, const __nv_bfloat16* __restrict__ Bl,
                 float* __restrict__ C, int M, int K)
{
    extern __shared__ __align__(128) char sm[];
    const uint32_t sb = smem_u32(sm);
    const int t = threadIdx.x, wid = t >> 5, lane = t & 31;
    const int m0 = blockIdx.y * BM, n0 = blockIdx.x * BN;
    const int NC = K / BK;
    const int wr = wid & 1, wc = wid >> 1;     // warp grid 2 x 4

    // per-thread load mapping: 2 chunks per tile (512 chunks of 16B per tile)
    const int lr0 = t >> 2;            // row for i=0 (0..63)
    const int lch = t & 3;             // chunk 0..3

    // per-lane ldmatrix offsets
    const int g = lane >> 3, lrw = lane & 7;
    const uint32_t a_off = (uint32_t)(((g & 1) * 8 + lrw) * PITCH + (g >> 1) * 16);
    const uint32_t b_off = (uint32_t)(((g >> 1) * 8 + lrw) * PITCH + (g & 1) * 16);

    float acc[4][4][4];
    #pragma unroll
    for (int mt = 0; mt < 4; mt++)
        #pragma unroll
        for (int ng = 0; ng < 4; ng++)
            #pragma unroll
            for (int q = 0; q < 4; q++) acc[mt][ng][q] = 0.0f;

    // stage issue
    auto issue = [&](int c) {
        const int buf = c & 1;
        const uint32_t stg = sb + buf * STAGE;
        const int kt = c * BK;
        #pragma unroll
        for (int i = 0; i < 2; i++) {
            const int r = lr0 + i * 64;
            const uint32_t doff = (uint32_t)(r * PITCH + lch * 16);
            const size_t sa = (size_t)(m0 + r) * K + kt + lch * 8;
            const size_t sbi = (size_t)(n0 + r) * K + kt + lch * 8;
            CP_ASYNC16(stg + doff,               Ah + sa);
            CP_ASYNC16(stg + TILE_B + doff,      Al + sa);
            CP_ASYNC16(stg + 2 * TILE_B + doff,  Bh + sbi);
            CP_ASYNC16(stg + 3 * TILE_B + doff,  Bl + sbi);
        }
        CP_COMMIT();
    };

    issue(0);

    for (int c = 0; c < NC; c++) {
        if (c + 1 < NC) { issue(c + 1); CP_WAIT(1); }
        else            { CP_WAIT(0); }
        __syncthreads();

        const uint32_t stg = sb + (c & 1) * STAGE;
        const uint32_t aH = stg + (uint32_t)(wr * 64) * PITCH;
        const uint32_t aL = aH + TILE_B;
        const uint32_t bH = stg + 2 * TILE_B + (uint32_t)(wc * 32) * PITCH;
        const uint32_t bL = bH + TILE_B;

        #pragma unroll
        for (int ks = 0; ks < 2; ks++) {
            const uint32_t kb = (uint32_t)(ks * 32);
            uint32_t fAh[4][4], fAl[4][4], fBh[4][2], fBl[4][2];
            #pragma unroll
            for (int mt = 0; mt < 4; mt++) {
                uint32_t ad = aH + (uint32_t)(mt * 16) * PITCH + kb + a_off;
                LDM_X4(fAh[mt][0], fAh[mt][1], fAh[mt][2], fAh[mt][3], ad);
                uint32_t ad2 = aL + (uint32_t)(mt * 16) * PITCH + kb + a_off;
                LDM_X4(fAl[mt][0], fAl[mt][1], fAl[mt][2], fAl[mt][3], ad2);
            }
            #pragma unroll
            for (int nt = 0; nt < 2; nt++) {
                uint32_t bd = bH + (uint32_t)(nt * 16) * PITCH + kb + b_off;
                uint32_t r0, r1, r2, r3;
                LDM_X4(r0, r1, r2, r3, bd);
                fBh[nt * 2][0] = r0; fBh[nt * 2][1] = r1;
                fBh[nt * 2 + 1][0] = r2; fBh[nt * 2 + 1][1] = r3;
                uint32_t bd2 = bL + (uint32_t)(nt * 16) * PITCH + kb + b_off;
                LDM_X4(r0, r1, r2, r3, bd2);
                fBl[nt * 2][0] = r0; fBl[nt * 2][1] = r1;
                fBl[nt * 2 + 1][0] = r2; fBl[nt * 2 + 1][1] = r3;
            }
            #pragma unroll
            for (int mt = 0; mt < 4; mt++) {
                #pragma unroll
                for (int ng = 0; ng < 4; ng++) {
                    MMA_BF16(acc[mt][ng], fAh[mt], fBh[ng]);
                    MMA_BF16(acc[mt][ng], fAh[mt], fBl[ng]);
                    MMA_BF16(acc[mt][ng], fAl[mt], fBh[ng]);
                }
            }
        }
        __syncthreads();
    }

    // Epilogue: direct fp32 stores
    const int row0 = m0 + wr * 64 + lane / 4;
    const int col0 = n0 + wc * 32 + (lane % 4) * 2;
    #pragma unroll
    for (int mt = 0; mt < 4; mt++) {
        #pragma unroll
        for (int ng = 0; ng < 4; ng++) {
            float* p = C + (size_t)(row0 + mt * 16) * DIM + col0 + ng * 8;
            *(float2*)p = make_float2(acc[mt][ng][0], acc[mt][ng][1]);
            *(float2*)(p + 8 * DIM) = make_float2(acc[mt][ng][2], acc[mt][ng][3]);
        }
    }
}

// ---------------------------------------------------------------------------
// Fused attention per (b, h): 64 Q-rows per block, full M=256 keys in smem.
// In-register softmax via half-warp shuffles; conflict-free K reads.
// ---------------------------------------------------------------------------
#define QS_LD 65
#define KT_LD 260
#define SS_LD 260

__global__ void __launch_bounds__(256, 1)
attn_kernel(const float* __restrict__ Q, const float* __restrict__ Kg,
            const float* __restrict__ Vg, const int* __restrict__ maskp,
            float* __restrict__ O)
{
    extern __shared__ float smf[];
    float* Qs = smf;                     // [64][65]
    float* Kt = Qs + 64 * QS_LD;         // [64][260]  (K transposed)
    float* Ss = Kt + 64 * KT_LD;         // [64][260]  (P)
    float* Vs = Ss + 64 * SS_LD;         // [256][64]
    int*   Ms = (int*)(Vs + 256 * 64);   // [256]

    const int t  = threadIdx.x;
    const int b  = blockIdx.y >> 4;
    const int h  = blockIdx.y & 15;
    const int n0 = blockIdx.x * 64;

    const float* Qbase = Q  + ((size_t)(b * SEQ_N + n0) * DIM) + h * HD;
    const float* Kbase = Kg + ((size_t)(b * SEQ_M) * DIM) + h * HD;
    const float* Vbase = Vg + ((size_t)(b * SEQ_M) * DIM) + h * HD;

    #pragma unroll
    for (int i = 0; i < 4; i++) {
        int lin = t + i * 256;
        int r = lin >> 4, c4 = lin & 15;
        float4 f = *(const float4*)(Qbase + (size_t)r * DIM + c4 * 4);
        float* dst = &Qs[r * QS_LD + c4 * 4];
        dst[0] = f.x; dst[1] = f.y; dst[2] = f.z; dst[3] = f.w;
    }
    #pragma unroll
    for (int i = 0; i < 16; i++) {
        int lin = t + i * 256;
        int j = lin >> 4, c4 = lin & 15;
        float4 f = *(const float4*)(Kbase + (size_t)j * DIM + c4 * 4);
        int k = c4 * 4;
        Kt[(k + 0) * KT_LD + j] = f.x;
        Kt[(k + 1) * KT_LD + j] = f.y;
        Kt[(k + 2) * KT_LD + j] = f.z;
        Kt[(k + 3) * KT_LD + j] = f.w;
        float4 gq = *(const float4*)(Vbase + (size_t)j * DIM + c4 * 4);
        *(float4*)&Vs[j * 64 + c4 * 4] = gq;
    }
    Ms[t] = maskp[b * SEQ_M + t];
    __syncthreads();

    // Phase 1: S = Q @ K^T; thread (tr, tc) owns rows tr*4..+3, cols tc*4 + uu*64 + vv
    const int tc = t & 15;
    const int tr = t >> 4;
    float s[4][16];
    #pragma unroll
    for (int i = 0; i < 4; i++)
        #pragma unroll
        for (int u = 0; u < 16; u++) s[i][u] = 0.0f;

    #pragma unroll 4
    for (int k = 0; k < 64; k++) {
        float a0 = Qs[(tr * 4 + 0) * QS_LD + k];
        float a1 = Qs[(tr * 4 + 1) * QS_LD + k];
        float a2 = Qs[(tr * 4 + 2) * QS_LD + k];
        float a3 = Qs[(tr * 4 + 3) * QS_LD + k];
        float bv[16];
        #pragma unroll
        for (int uu = 0; uu < 4; uu++) {
            float4 bq = *(const float4*)&Kt[k * KT_LD + tc * 4 + uu * 64];
            bv[uu * 4 + 0] = bq.x; bv[uu * 4 + 1] = bq.y;
            bv[uu * 4 + 2] = bq.z; bv[uu * 4 + 3] = bq.w;
        }
        #pragma unroll
        for (int u = 0; u < 16; u++) {
            s[0][u] = fmaf(a0, bv[u], s[0][u]);
            s[1][u] = fmaf(a1, bv[u], s[1][u]);
            s[2][u] = fmaf(a2, bv[u], s[2][u]);
            s[3][u] = fmaf(a3, bv[u], s[3][u]);
        }
    }

    // mask + scale + in-register softmax (row = 16 lanes of a half-warp)
    float keep[16];
    #pragma unroll
    for (int u = 0; u < 16; u++)
        keep[u] = Ms[tc * 4 + (u >> 2) * 64 + (u & 3)] ? 1.0f : 0.0f;

    const float scale = 0.125f;
    #pragma unroll
    for (int i = 0; i < 4; i++) {
        int r = tr * 4 + i;
        float m = -INFINITY;
        #pragma unroll
        for (int u = 0; u < 16; u++) {
            s[i][u] = keep[u] ? s[i][u] * scale : -1e30f;
            m = fmaxf(m, s[i][u]);
        }
        m = fmaxf(m, __shfl_xor_sync(0xffffffffu, m, 1));
        m = fmaxf(m, __shfl_xor_sync(0xffffffffu, m, 2));
        m = fmaxf(m, __shfl_xor_sync(0xffffffffu, m, 4));
        m = fmaxf(m, __shfl_xor_sync(0xffffffffu, m, 8));
        float sum = 0.0f;
        #pragma unroll
        for (int u = 0; u < 16; u++) {
            s[i][u] = __expf(s[i][u] - m);
            sum += s[i][u];
        }
        sum += __shfl_xor_sync(0xffffffffu, sum, 1);
        sum += __shfl_xor_sync(0xffffffffu, sum, 2);
        sum += __shfl_xor_sync(0xffffffffu, sum, 4);
        sum += __shfl_xor_sync(0xffffffffu, sum, 8);
        float inv = 1.0f / sum;
        #pragma unroll
        for (int uu = 0; uu < 4; uu++) {
            *(float4*)&Ss[r * SS_LD + tc * 4 + uu * 64] =
                make_float4(s[i][uu * 4 + 0] * inv, s[i][uu * 4 + 1] * inv,
                            s[i][uu * 4 + 2] * inv, s[i][uu * 4 + 3] * inv);
        }
    }
    __syncthreads();

    // Phase 3: O = P @ V
    float o[4][4];
    #pragma unroll
    for (int i = 0; i < 4; i++)
        #pragma unroll
        for (int u = 0; u < 4; u++) o[i][u] = 0.0f;

    #pragma unroll 8
    for (int j = 0; j < 256; j++) {
        float a0 = Ss[(tr * 4 + 0) * SS_LD + j];
        float a1 = Ss[(tr * 4 + 1) * SS_LD + j];
        float a2 = Ss[(tr * 4 + 2) * SS_LD + j];
        float a3 = Ss[(tr * 4 + 3) * SS_LD + j];
        float4 bv = *(const float4*)&Vs[j * 64 + tc * 4];
        o[0][0] = fmaf(a0, bv.x, o[0][0]); o[0][1] = fmaf(a0, bv.y, o[0][1]);
        o[0][2] = fmaf(a0, bv.z, o[0][2]); o[0][3] = fmaf(a0, bv.w, o[0][3]);
        o[1][0] = fmaf(a1, bv.x, o[1][0]); o[1][1] = fmaf(a1, bv.y, o[1][1]);
        o[1][2] = fmaf(a1, bv.z, o[1][2]); o[1][3] = fmaf(a1, bv.w, o[1][3]);
        o[2][0] = fmaf(a2, bv.x, o[2][0]); o[2][1] = fmaf(a2, bv.y, o[2][1]);
        o[2][2] = fmaf(a2, bv.z, o[2][2]); o[2][3] = fmaf(a2, bv.w, o[2][3]);
        o[3][0] = fmaf(a3, bv.x, o[3][0]); o[3][1] = fmaf(a3, bv.y, o[3][1]);
        o[3][2] = fmaf(a3, bv.z, o[3][2]); o[3][3] = fmaf(a3, bv.w, o[3][3]);
    }

    float* Ob = O + ((size_t)(b * SEQ_N + n0) * DIM) + h * HD;
    #pragma unroll
    for (int i = 0; i < 4; i++) {
        *(float4*)(Ob + (size_t)(tr * 4 + i) * DIM + tc * 4) =
            make_float4(o[i][0], o[i][1], o[i][2], o[i][3]);
    }
}

// ---------------------------------------------------------------------------
// Host launcher
// ---------------------------------------------------------------------------
extern "C" void kernel_launch(void* const* d_in, const int* in_sizes, int n_in,
                              void* d_out, int out_size)
{
    const float* x    = (const float*)d_in[0];
    const float* ctx  = (const float*)d_in[1];
    const int*   mask = (const int*)d_in[2];
    const float* Wq   = (const float*)d_in[3];
    const float* Wk   = (const float*)d_in[4];
    const float* Wv   = (const float*)d_in[5];
    const float* Wo   = (const float*)d_in[6];
    float*       out  = (float*)d_out;

    float *Qg, *Kg, *Vg, *ATg;
    __nv_bfloat16 *Ahp, *Alp, *Chp, *Clp, *Bhp, *Blp;
    cudaGetSymbolAddress((void**)&Qg,  g_Q);
    cudaGetSymbolAddress((void**)&Kg,  g_K);
    cudaGetSymbolAddress((void**)&Vg,  g_V);
    cudaGetSymbolAddress((void**)&ATg, g_AT);
    cudaGetSymbolAddress((void**)&Ahp, g_Ah);
    cudaGetSymbolAddress((void**)&Alp, g_Al);
    cudaGetSymbolAddress((void**)&Chp, g_Ch);
    cudaGetSymbolAddress((void**)&Clp, g_Cl);
    cudaGetSymbolAddress((void**)&Bhp, g_Bh);
    cudaGetSymbolAddress((void**)&Blp, g_Bl);

    cudaFuncSetAttribute(gemm_hmma_kernel, cudaFuncAttributeMaxDynamicSharedMemorySize, GEMM_SMEM);

    const int n4x = ROWS_X * DIM / 4;
    const int n4c = ROWS_C * CTX_DIM / 4;
    dim3 tb32(32, 8);

    // Q projection
    split_kernel<<<n4x / 256, 256>>>(x, Ahp, Alp, n4x);
    transpose_split_kernel<<<dim3(DIM / 32, DIM / 32), tb32>>>(Wq, Bhp, Blp, DIM, DIM);
    gemm_hmma_kernel<<<dim3(DIM / BN, ROWS_X / BM), 256, GEMM_SMEM>>>(Ahp, Alp, Bhp, Blp, Qg, ROWS_X, DIM);

    // K projection
    split_kernel<<<n4c / 256, 256>>>(ctx, Chp, Clp, n4c);
    transpose_split_kernel<<<dim3(DIM / 32, CTX_DIM / 32), tb32>>>(Wk, Bhp, Blp, CTX_DIM, DIM);
    gemm_hmma_kernel<<<dim3(DIM / BN, ROWS_C / BM), 256, GEMM_SMEM>>>(Chp, Clp, Bhp, Blp, Kg, ROWS_C, CTX_DIM);

    // V projection
    transpose_split_kernel<<<dim3(DIM / 32, CTX_DIM / 32), tb32>>>(Wv, Bhp, Blp, CTX_DIM, DIM);
    gemm_hmma_kernel<<<dim3(DIM / BN, ROWS_C / BM), 256, GEMM_SMEM>>>(Chp, Clp, Bhp, Blp, Vg, ROWS_C, CTX_DIM);

    // Attention
    size_t attn_smem = (size_t)(64 * QS_LD + 64 * KT_LD + 64 * SS_LD + 256 * 64) * sizeof(float) + 1024;
    cudaFuncSetAttribute(attn_kernel, cudaFuncAttributeMaxDynamicSharedMemorySize, (int)attn_smem);
    attn_kernel<<<dim3(SEQ_N / 64, BATCH * HEADS), 256, attn_smem>>>(Qg, Kg, Vg, mask, ATg);

    // O projection
    split_kernel<<<n4x / 256, 256>>>(ATg, Ahp, Alp, n4x);
    transpose_split_kernel<<<dim3(DIM / 32, DIM / 32), tb32>>>(Wo, Bhp, Blp, DIM, DIM);
    gemm_hmma_kernel<<<dim3(DIM / BN, ROWS_X / BM), 256, GEMM_SMEM>>>(Ahp, Alp, Bhp, Blp, out, ROWS_X, DIM);
}

// round 5
// speedup vs baseline: 2.6472x; 1.3332x over previous
#include <cuda_runtime.h>
#include <cuda_bf16.h>
#include <math.h>
#include <stdint.h>

// Problem constants
#define BATCH 4
#define SEQ_N 4096
#define SEQ_M 256
#define DIM 1024
#define CTX_DIM 768
#define HEADS 16
#define HD 64
#define ROWS_X (BATCH * SEQ_N)      // 16384
#define ROWS_C (BATCH * SEQ_M)      // 1024

// Scratch (device globals)
__device__ __nv_bfloat16 g_Ah[ROWS_X * DIM];   // x split / attn-out split
__device__ __nv_bfloat16 g_Al[ROWS_X * DIM];
__device__ __nv_bfloat16 g_Ch[ROWS_C * CTX_DIM];
__device__ __nv_bfloat16 g_Cl[ROWS_C * CTX_DIM];
__device__ __nv_bfloat16 g_Bh[DIM * DIM];
__device__ __nv_bfloat16 g_Bl[DIM * DIM];
__device__ __nv_bfloat16 g_Qh[ROWS_X * DIM];
__device__ __nv_bfloat16 g_Ql[ROWS_X * DIM];
__device__ __nv_bfloat16 g_Kh[ROWS_C * DIM];
__device__ __nv_bfloat16 g_Kl[ROWS_C * DIM];
__device__ __nv_bfloat16 g_Vh[ROWS_C * DIM];
__device__ __nv_bfloat16 g_Vl[ROWS_C * DIM];

// ---------------------------------------------------------------------------
// PTX helpers (sm_80+ portable)
// ---------------------------------------------------------------------------
__device__ __forceinline__ uint32_t smem_u32(const void* p) {
    uint32_t a;
    asm("{ .reg .u64 t; cvta.to.shared.u64 t, %1; cvt.u32.u64 %0, t; }" : "=r"(a) : "l"(p));
    return a;
}
#define CP_ASYNC16(dst, src) \
    asm volatile("cp.async.cg.shared.global [%0], [%1], 16;" :: "r"(dst), "l"(src))
#define CP_COMMIT() asm volatile("cp.async.commit_group;" ::: "memory")
#define CP_WAIT(n)  asm volatile("cp.async.wait_group %0;" :: "n"(n) : "memory")

#define LDM_X4(r0, r1, r2, r3, a) \
    asm volatile("ldmatrix.sync.aligned.m8n8.x4.shared.b16 {%0,%1,%2,%3}, [%4];" \
                 : "=r"(r0), "=r"(r1), "=r"(r2), "=r"(r3) : "r"(a))
#define LDM_X4T(r0, r1, r2, r3, a) \
    asm volatile("ldmatrix.sync.aligned.m8n8.x4.trans.shared.b16 {%0,%1,%2,%3}, [%4];" \
                 : "=r"(r0), "=r"(r1), "=r"(r2), "=r"(r3) : "r"(a))

#define MMA_BF16(d, a, b) \
    asm volatile("mma.sync.aligned.m16n8k16.row.col.f32.bf16.bf16.f32 " \
                 "{%0,%1,%2,%3},{%4,%5,%6,%7},{%8,%9},{%0,%1,%2,%3};" \
                 : "+f"((d)[0]), "+f"((d)[1]), "+f"((d)[2]), "+f"((d)[3]) \
                 : "r"((a)[0]), "r"((a)[1]), "r"((a)[2]), "r"((a)[3]), \
                   "r"((b)[0]), "r"((b)[1]))

__device__ __forceinline__ void split2(float x, float y, uint32_t& h, uint32_t& l) {
    __nv_bfloat162 hb = __float22bfloat162_rn(make_float2(x, y));
    float2 hf = __bfloat1622float2(hb);
    __nv_bfloat162 lb = __float22bfloat162_rn(make_float2(x - hf.x, y - hf.y));
    h = *(uint32_t*)&hb;
    l = *(uint32_t*)&lb;
}

// ---------------------------------------------------------------------------
// fp32 -> bf16 hi/lo split
// ---------------------------------------------------------------------------
__global__ void split_kernel(const float* __restrict__ X, __nv_bfloat16* __restrict__ Xh,
                             __nv_bfloat16* __restrict__ Xl, int n4)
{
    int i = blockIdx.x * blockDim.x + threadIdx.x;
    if (i >= n4) return;
    float4 v = ((const float4*)X)[i];
    float a[4] = {v.x, v.y, v.z, v.w};
    __nv_bfloat16 h[4], l[4];
    #pragma unroll
    for (int j = 0; j < 4; j++) {
        h[j] = __float2bfloat16(a[j]);
        l[j] = __float2bfloat16(a[j] - __bfloat162float(h[j]));
    }
    __nv_bfloat162* Hp = (__nv_bfloat162*)(Xh + 4 * (size_t)i);
    __nv_bfloat162* Lp = (__nv_bfloat162*)(Xl + 4 * (size_t)i);
    Hp[0] = __nv_bfloat162(h[0], h[1]); Hp[1] = __nv_bfloat162(h[2], h[3]);
    Lp[0] = __nv_bfloat162(l[0], l[1]); Lp[1] = __nv_bfloat162(l[2], l[3]);
}

// ---------------------------------------------------------------------------
// W[K][N] -> Th/Tl[N][K] bf16 hi/lo (transpose + split)
// ---------------------------------------------------------------------------
__global__ void transpose_split_kernel(const float* __restrict__ W, __nv_bfloat16* __restrict__ Th,
                                       __nv_bfloat16* __restrict__ Tl, int K, int N)
{
    __shared__ float tile[32][33];
    int n0 = blockIdx.x * 32, k0 = blockIdx.y * 32;
    int tx = threadIdx.x, ty = threadIdx.y;
    #pragma unroll
    for (int j = ty; j < 32; j += 8)
        tile[j][tx] = W[(size_t)(k0 + j) * N + n0 + tx];
    __syncthreads();
    #pragma unroll
    for (int j = ty; j < 32; j += 8) {
        float v = tile[tx][j];
        __nv_bfloat16 h = __float2bfloat16(v);
        __nv_bfloat16 l = __float2bfloat16(v - __bfloat162float(h));
        size_t o = (size_t)(n0 + j) * K + k0 + tx;
        Th[o] = h; Tl[o] = l;
    }
}

// ---------------------------------------------------------------------------
// HMMA bf16-split GEMM: C[M, 1024] = A[M,K] @ W[K,1024]
// SPLIT=0: fp32 out. SPLIT=1: bf16 hi/lo out (Ch/Cl).
// ---------------------------------------------------------------------------
#define BM 128
#define BN 128
#define BK 32
#define PITCH 80
#define TILE_B (128 * PITCH)
#define STAGE  (4 * TILE_B)
#define GEMM_SMEM (2 * STAGE)

template<int SPLIT>
__global__ void __launch_bounds__(256, 1)
gemm_hmma_kernel(const __nv_bfloat16* __restrict__ Ah, const __nv_bfloat16* __restrict__ Al,
                 const __nv_bfloat16* __restrict__ Bh, const __nv_bfloat16* __restrict__ Bl,
                 float* __restrict__ C, __nv_bfloat16* __restrict__ Ch,
                 __nv_bfloat16* __restrict__ Cl, int M, int K)
{
    extern __shared__ __align__(128) char sm[];
    const uint32_t sb = smem_u32(sm);
    const int t = threadIdx.x, wid = t >> 5, lane = t & 31;
    const int m0 = blockIdx.y * BM, n0 = blockIdx.x * BN;
    const int NC = K / BK;
    const int wr = wid & 1, wc = wid >> 1;

    const int lr0 = t >> 2;
    const int lch = t & 3;

    const int g = lane >> 3, lrw = lane & 7;
    const uint32_t a_off = (uint32_t)(((g & 1) * 8 + lrw) * PITCH + (g >> 1) * 16);
    const uint32_t b_off = (uint32_t)(((g >> 1) * 8 + lrw) * PITCH + (g & 1) * 16);

    float acc[4][4][4];
    #pragma unroll
    for (int mt = 0; mt < 4; mt++)
        #pragma unroll
        for (int ng = 0; ng < 4; ng++)
            #pragma unroll
            for (int q = 0; q < 4; q++) acc[mt][ng][q] = 0.0f;

    auto issue = [&](int c) {
        const int buf = c & 1;
        const uint32_t stg = sb + buf * STAGE;
        const int kt = c * BK;
        #pragma unroll
        for (int i = 0; i < 2; i++) {
            const int r = lr0 + i * 64;
            const uint32_t doff = (uint32_t)(r * PITCH + lch * 16);
            const size_t sa = (size_t)(m0 + r) * K + kt + lch * 8;
            const size_t sbi = (size_t)(n0 + r) * K + kt + lch * 8;
            CP_ASYNC16(stg + doff,               Ah + sa);
            CP_ASYNC16(stg + TILE_B + doff,      Al + sa);
            CP_ASYNC16(stg + 2 * TILE_B + doff,  Bh + sbi);
            CP_ASYNC16(stg + 3 * TILE_B + doff,  Bl + sbi);
        }
        CP_COMMIT();
    };

    issue(0);

    for (int c = 0; c < NC; c++) {
        if (c + 1 < NC) { issue(c + 1); CP_WAIT(1); }
        else            { CP_WAIT(0); }
        __syncthreads();

        const uint32_t stg = sb + (c & 1) * STAGE;
        const uint32_t aH = stg + (uint32_t)(wr * 64) * PITCH;
        const uint32_t aL = aH + TILE_B;
        const uint32_t bH = stg + 2 * TILE_B + (uint32_t)(wc * 32) * PITCH;
        const uint32_t bL = bH + TILE_B;

        #pragma unroll
        for (int ks = 0; ks < 2; ks++) {
            const uint32_t kb = (uint32_t)(ks * 32);
            uint32_t fAh[4][4], fAl[4][4], fBh[4][2], fBl[4][2];
            #pragma unroll
            for (int mt = 0; mt < 4; mt++) {
                uint32_t ad = aH + (uint32_t)(mt * 16) * PITCH + kb + a_off;
                LDM_X4(fAh[mt][0], fAh[mt][1], fAh[mt][2], fAh[mt][3], ad);
                uint32_t ad2 = aL + (uint32_t)(mt * 16) * PITCH + kb + a_off;
                LDM_X4(fAl[mt][0], fAl[mt][1], fAl[mt][2], fAl[mt][3], ad2);
            }
            #pragma unroll
            for (int nt = 0; nt < 2; nt++) {
                uint32_t bd = bH + (uint32_t)(nt * 16) * PITCH + kb + b_off;
                uint32_t r0, r1, r2, r3;
                LDM_X4(r0, r1, r2, r3, bd);
                fBh[nt * 2][0] = r0; fBh[nt * 2][1] = r1;
                fBh[nt * 2 + 1][0] = r2; fBh[nt * 2 + 1][1] = r3;
                uint32_t bd2 = bL + (uint32_t)(nt * 16) * PITCH + kb + b_off;
                LDM_X4(r0, r1, r2, r3, bd2);
                fBl[nt * 2][0] = r0; fBl[nt * 2][1] = r1;
                fBl[nt * 2 + 1][0] = r2; fBl[nt * 2 + 1][1] = r3;
            }
            #pragma unroll
            for (int mt = 0; mt < 4; mt++) {
                #pragma unroll
                for (int ng = 0; ng < 4; ng++) {
                    MMA_BF16(acc[mt][ng], fAh[mt], fBh[ng]);
                    MMA_BF16(acc[mt][ng], fAh[mt], fBl[ng]);
                    MMA_BF16(acc[mt][ng], fAl[mt], fBh[ng]);
                }
            }
        }
        __syncthreads();
    }

    const int row0 = m0 + wr * 64 + lane / 4;
    const int col0 = n0 + wc * 32 + (lane % 4) * 2;
    #pragma unroll
    for (int mt = 0; mt < 4; mt++) {
        #pragma unroll
        for (int ng = 0; ng < 4; ng++) {
            size_t o1 = (size_t)(row0 + mt * 16) * DIM + col0 + ng * 8;
            size_t o2 = o1 + 8 * DIM;
            if (SPLIT) {
                uint32_t h, l;
                split2(acc[mt][ng][0], acc[mt][ng][1], h, l);
                *(uint32_t*)(Ch + o1) = h; *(uint32_t*)(Cl + o1) = l;
                split2(acc[mt][ng][2], acc[mt][ng][3], h, l);
                *(uint32_t*)(Ch + o2) = h; *(uint32_t*)(Cl + o2) = l;
            } else {
                *(float2*)(C + o1) = make_float2(acc[mt][ng][0], acc[mt][ng][1]);
                *(float2*)(C + o2) = make_float2(acc[mt][ng][2], acc[mt][ng][3]);
            }
        }
    }
}

// ---------------------------------------------------------------------------
// HMMA flash-attention per (b, h): 64 Q-rows per CTA, all 256 keys in smem.
// Warp grid: wm = wid&3 (16 Q-rows each), wn = wid>>2 (128 keys each).
// S = QK^T bf16-split (3 MMAs); softmax on fragments; O = P V with split P.
// Writes output directly as bf16 hi/lo (input to O-projection).
// ---------------------------------------------------------------------------
#define AP 144                      // smem row pitch bytes (64 bf16 -> 128B + 16 pad)
#define OFF_QH 0
#define OFF_QL 9216
#define OFF_KH 18432
#define OFF_KL 55296
#define OFF_VH 92160
#define OFF_VL 129024
#define OFF_RED 165888              // max [2][64] f32 (512B) + sum [2][64] (512B)
#define OFF_OC 166912               // 64 x 68 f32 combine buffer (17408B)
#define OFF_MS 184320               // 256 ints
#define ATTN_SMEM 185344

__global__ void __launch_bounds__(256, 1)
attn_hmma_kernel(const __nv_bfloat16* __restrict__ Qh, const __nv_bfloat16* __restrict__ Ql,
                 const __nv_bfloat16* __restrict__ Kh, const __nv_bfloat16* __restrict__ Kl,
                 const __nv_bfloat16* __restrict__ Vh, const __nv_bfloat16* __restrict__ Vl,
                 const int* __restrict__ maskp,
                 __nv_bfloat16* __restrict__ Oh, __nv_bfloat16* __restrict__ Ol)
{
    extern __shared__ __align__(128) char smc[];
    const uint32_t sb = smem_u32(smc);
    float* redbuf = (float*)(smc + OFF_RED);
    float* Ocomb  = (float*)(smc + OFF_OC);
    int*   Msm    = (int*)(smc + OFF_MS);

    const int t = threadIdx.x, wid = t >> 5, lane = t & 31;
    const int b = blockIdx.y >> 4, h = blockIdx.y & 15;
    const int n0 = blockIdx.x * 64;

    // ---- load tiles via cp.async ----
    #pragma unroll
    for (int i = 0; i < 2; i++) {
        int idx = t + i * 256;          // < 512
        int r = idx >> 3, ch = idx & 7;
        uint32_t doff = (uint32_t)(r * AP + ch * 16);
        size_t src = (size_t)(b * SEQ_N + n0 + r) * DIM + h * HD + ch * 8;
        CP_ASYNC16(sb + OFF_QH + doff, Qh + src);
        CP_ASYNC16(sb + OFF_QL + doff, Ql + src);
    }
    #pragma unroll
    for (int i = 0; i < 8; i++) {
        int idx = t + i * 256;          // < 2048
        int r = idx >> 3, ch = idx & 7;
        uint32_t doff = (uint32_t)(r * AP + ch * 16);
        size_t src = (size_t)(b * SEQ_M + r) * DIM + h * HD + ch * 8;
        CP_ASYNC16(sb + OFF_KH + doff, Kh + src);
        CP_ASYNC16(sb + OFF_KL + doff, Kl + src);
        CP_ASYNC16(sb + OFF_VH + doff, Vh + src);
        CP_ASYNC16(sb + OFF_VL + doff, Vl + src);
    }
    CP_COMMIT();
    Msm[t] = maskp[b * SEQ_M + t];
    CP_WAIT(0);
    __syncthreads();

    const int wm = wid & 3, wn = wid >> 2;
    const int g = lane >> 3, lrw = lane & 7;
    const uint32_t a_off = (uint32_t)(((g & 1) * 8 + lrw) * AP + (g >> 1) * 16);
    const uint32_t b_off = (uint32_t)(((g >> 1) * 8 + lrw) * AP + (g & 1) * 16);

    // ---- Phase 1: S = Q K^T  (acc[j] covers keys wn*128 + j*8) ----
    float acc[16][4];
    #pragma unroll
    for (int j = 0; j < 16; j++)
        #pragma unroll
        for (int q = 0; q < 4; q++) acc[j][q] = 0.0f;

    #pragma unroll
    for (int ks = 0; ks < 4; ks++) {
        const uint32_t kb = (uint32_t)(ks * 32);
        uint32_t fAh[4], fAl[4];
        uint32_t aH = sb + OFF_QH + (uint32_t)(wm * 16) * AP + kb + a_off;
        uint32_t aL = sb + OFF_QL + (uint32_t)(wm * 16) * AP + kb + a_off;
        LDM_X4(fAh[0], fAh[1], fAh[2], fAh[3], aH);
        LDM_X4(fAl[0], fAl[1], fAl[2], fAl[3], aL);
        #pragma unroll
        for (int nt = 0; nt < 8; nt++) {
            uint32_t kH = sb + OFF_KH + (uint32_t)((wn * 128 + nt * 16)) * AP + kb + b_off;
            uint32_t kL = sb + OFF_KL + (uint32_t)((wn * 128 + nt * 16)) * AP + kb + b_off;
            uint32_t h0, h1, h2, h3, l0, l1, l2, l3;
            LDM_X4(h0, h1, h2, h3, kH);
            LDM_X4(l0, l1, l2, l3, kL);
            uint32_t bh0[2] = {h0, h1}, bh1[2] = {h2, h3};
            uint32_t bl0[2] = {l0, l1}, bl1[2] = {l2, l3};
            MMA_BF16(acc[nt * 2],     fAh, bh0);
            MMA_BF16(acc[nt * 2],     fAh, bl0);
            MMA_BF16(acc[nt * 2],     fAl, bh0);
            MMA_BF16(acc[nt * 2 + 1], fAh, bh1);
            MMA_BF16(acc[nt * 2 + 1], fAh, bl1);
            MMA_BF16(acc[nt * 2 + 1], fAl, bh1);
        }
    }

    // ---- mask + scale + softmax ----
    const float scale = 0.125f;
    float m1 = -INFINITY, m2 = -INFINITY;
    #pragma unroll
    for (int j = 0; j < 16; j++) {
        int cb = wn * 128 + j * 8 + (lane & 3) * 2;
        bool k0 = Msm[cb] != 0, k1 = Msm[cb + 1] != 0;
        acc[j][0] = k0 ? acc[j][0] * scale : -1e30f;
        acc[j][1] = k1 ? acc[j][1] * scale : -1e30f;
        acc[j][2] = k0 ? acc[j][2] * scale : -1e30f;
        acc[j][3] = k1 ? acc[j][3] * scale : -1e30f;
        m1 = fmaxf(m1, fmaxf(acc[j][0], acc[j][1]));
        m2 = fmaxf(m2, fmaxf(acc[j][2], acc[j][3]));
    }
    m1 = fmaxf(m1, __shfl_xor_sync(0xffffffffu, m1, 1));
    m1 = fmaxf(m1, __shfl_xor_sync(0xffffffffu, m1, 2));
    m2 = fmaxf(m2, __shfl_xor_sync(0xffffffffu, m2, 1));
    m2 = fmaxf(m2, __shfl_xor_sync(0xffffffffu, m2, 2));

    const int r1 = wm * 16 + (lane >> 2), r2 = r1 + 8;
    if ((lane & 3) == 0) {
        redbuf[wn * 64 + r1] = m1;
        redbuf[wn * 64 + r2] = m2;
    }
    __syncthreads();
    const float M1 = fmaxf(m1, redbuf[(1 - wn) * 64 + r1]);
    const float M2 = fmaxf(m2, redbuf[(1 - wn) * 64 + r2]);

    float s1 = 0.0f, s2 = 0.0f;
    #pragma unroll
    for (int j = 0; j < 16; j++) {
        acc[j][0] = __expf(acc[j][0] - M1);
        acc[j][1] = __expf(acc[j][1] - M1);
        acc[j][2] = __expf(acc[j][2] - M2);
        acc[j][3] = __expf(acc[j][3] - M2);
        s1 += acc[j][0] + acc[j][1];
        s2 += acc[j][2] + acc[j][3];
    }
    s1 += __shfl_xor_sync(0xffffffffu, s1, 1);
    s1 += __shfl_xor_sync(0xffffffffu, s1, 2);
    s2 += __shfl_xor_sync(0xffffffffu, s2, 1);
    s2 += __shfl_xor_sync(0xffffffffu, s2, 2);
    float* sumbuf = redbuf + 128;
    if ((lane & 3) == 0) {
        sumbuf[wn * 64 + r1] = s1;
        sumbuf[wn * 64 + r2] = s2;
    }
    __syncthreads();
    const float inv1 = 1.0f / (s1 + sumbuf[(1 - wn) * 64 + r1]);
    const float inv2 = 1.0f / (s2 + sumbuf[(1 - wn) * 64 + r2]);

    // ---- Phase 3: O = P V (partial over this warp's 128 keys) ----
    float o[8][4];
    #pragma unroll
    for (int j = 0; j < 8; j++)
        #pragma unroll
        for (int q = 0; q < 4; q++) o[j][q] = 0.0f;

    #pragma unroll
    for (int kk = 0; kk < 8; kk++) {
        const int j0 = kk * 2, j1 = j0 + 1;
        uint32_t ph[4], pl[4];
        split2(acc[j0][0] * inv1, acc[j0][1] * inv1, ph[0], pl[0]);
        split2(acc[j0][2] * inv2, acc[j0][3] * inv2, ph[1], pl[1]);
        split2(acc[j1][0] * inv1, acc[j1][1] * inv1, ph[2], pl[2]);
        split2(acc[j1][2] * inv2, acc[j1][3] * inv2, ph[3], pl[3]);

        const uint32_t vrow = (uint32_t)(wn * 128 + kk * 16 + (g & 1) * 8 + lrw) * AP;
        #pragma unroll
        for (int ngp = 0; ngp < 4; ngp++) {
            const uint32_t vcol = (uint32_t)(((g >> 1) * 8 + ngp * 16) * 2);
            uint32_t h0, h1, h2, h3, l0, l1, l2, l3;
            LDM_X4T(h0, h1, h2, h3, sb + OFF_VH + vrow + vcol);
            LDM_X4T(l0, l1, l2, l3, sb + OFF_VL + vrow + vcol);
            uint32_t vh0[2] = {h0, h1}, vh1[2] = {h2, h3};
            uint32_t vl0[2] = {l0, l1}, vl1[2] = {l2, l3};
            MMA_BF16(o[ngp * 2],     ph, vh0);
            MMA_BF16(o[ngp * 2],     ph, vl0);
            MMA_BF16(o[ngp * 2],     pl, vh0);
            MMA_BF16(o[ngp * 2 + 1], ph, vh1);
            MMA_BF16(o[ngp * 2 + 1], ph, vl1);
            MMA_BF16(o[ngp * 2 + 1], pl, vh1);
        }
    }

    // ---- combine the two wn halves and write split bf16 output ----
    if (wn == 1) {
        #pragma unroll
        for (int j = 0; j < 8; j++) {
            int col = j * 8 + (lane & 3) * 2;
            *(float2*)&Ocomb[r1 * 68 + col] = make_float2(o[j][0], o[j][1]);
            *(float2*)&Ocomb[r2 * 68 + col] = make_float2(o[j][2], o[j][3]);
        }
    }
    __syncthreads();
    if (wn == 0) {
        #pragma unroll
        for (int j = 0; j < 8; j++) {
            int col = j * 8 + (lane & 3) * 2;
            float2 p1 = *(float2*)&Ocomb[r1 * 68 + col];
            float2 p2 = *(float2*)&Ocomb[r2 * 68 + col];
            uint32_t hh, ll;
            size_t go1 = (size_t)(b * SEQ_N + n0 + r1) * DIM + h * HD + col;
            size_t go2 = (size_t)(b * SEQ_N + n0 + r2) * DIM + h * HD + col;
            split2(o[j][0] + p1.x, o[j][1] + p1.y, hh, ll);
            *(uint32_t*)(Oh + go1) = hh; *(uint32_t*)(Ol + go1) = ll;
            split2(o[j][2] + p2.x, o[j][3] + p2.y, hh, ll);
            *(uint32_t*)(Oh + go2) = hh; *(uint32_t*)(Ol + go2) = ll;
        }
    }
}

// ---------------------------------------------------------------------------
// Host launcher
// ---------------------------------------------------------------------------
extern "C" void kernel_launch(void* const* d_in, const int* in_sizes, int n_in,
                              void* d_out, int out_size)
{
    const float* x    = (const float*)d_in[0];
    const float* ctx  = (const float*)d_in[1];
    const int*   mask = (const int*)d_in[2];
    const float* Wq   = (const float*)d_in[3];
    const float* Wk   = (const float*)d_in[4];
    const float* Wv   = (const float*)d_in[5];
    const float* Wo   = (const float*)d_in[6];
    float*       out  = (float*)d_out;

    __nv_bfloat16 *Ahp, *Alp, *Chp, *Clp, *Bhp, *Blp, *Qhp, *Qlp, *Khp, *Klp, *Vhp, *Vlp;
    cudaGetSymbolAddress((void**)&Ahp, g_Ah);
    cudaGetSymbolAddress((void**)&Alp, g_Al);
    cudaGetSymbolAddress((void**)&Chp, g_Ch);
    cudaGetSymbolAddress((void**)&Clp, g_Cl);
    cudaGetSymbolAddress((void**)&Bhp, g_Bh);
    cudaGetSymbolAddress((void**)&Blp, g_Bl);
    cudaGetSymbolAddress((void**)&Qhp, g_Qh);
    cudaGetSymbolAddress((void**)&Qlp, g_Ql);
    cudaGetSymbolAddress((void**)&Khp, g_Kh);
    cudaGetSymbolAddress((void**)&Klp, g_Kl);
    cudaGetSymbolAddress((void**)&Vhp, g_Vh);
    cudaGetSymbolAddress((void**)&Vlp, g_Vl);

    cudaFuncSetAttribute(gemm_hmma_kernel<0>, cudaFuncAttributeMaxDynamicSharedMemorySize, GEMM_SMEM);
    cudaFuncSetAttribute(gemm_hmma_kernel<1>, cudaFuncAttributeMaxDynamicSharedMemorySize, GEMM_SMEM);
    cudaFuncSetAttribute(attn_hmma_kernel, cudaFuncAttributeMaxDynamicSharedMemorySize, ATTN_SMEM);

    const int n4x = ROWS_X * DIM / 4;
    const int n4c = ROWS_C * CTX_DIM / 4;
    dim3 tb32(32, 8);

    // Q projection -> split bf16
    split_kernel<<<n4x / 256, 256>>>(x, Ahp, Alp, n4x);
    transpose_split_kernel<<<dim3(DIM / 32, DIM / 32), tb32>>>(Wq, Bhp, Blp, DIM, DIM);
    gemm_hmma_kernel<1><<<dim3(DIM / BN, ROWS_X / BM), 256, GEMM_SMEM>>>(
        Ahp, Alp, Bhp, Blp, nullptr, Qhp, Qlp, ROWS_X, DIM);

    // K projection -> split bf16
    split_kernel<<<n4c / 256, 256>>>(ctx, Chp, Clp, n4c);
    transpose_split_kernel<<<dim3(DIM / 32, CTX_DIM / 32), tb32>>>(Wk, Bhp, Blp, CTX_DIM, DIM);
    gemm_hmma_kernel<1><<<dim3(DIM / BN, ROWS_C / BM), 256, GEMM_SMEM>>>(
        Chp, Clp, Bhp, Blp, nullptr, Khp, Klp, ROWS_C, CTX_DIM);

    // V projection -> split bf16
    transpose_split_kernel<<<dim3(DIM / 32, CTX_DIM / 32), tb32>>>(Wv, Bhp, Blp, CTX_DIM, DIM);
    gemm_hmma_kernel<1><<<dim3(DIM / BN, ROWS_C / BM), 256, GEMM_SMEM>>>(
        Chp, Clp, Bhp, Blp, nullptr, Vhp, Vlp, ROWS_C, CTX_DIM);

    // Flash attention -> writes split bf16 into g_Ah/g_Al
    attn_hmma_kernel<<<dim3(SEQ_N / 64, BATCH * HEADS), 256, ATTN_SMEM>>>(
        Qhp, Qlp, Khp, Klp, Vhp, Vlp, mask, Ahp, Alp);

    // O projection -> fp32 final output
    transpose_split_kernel<<<dim3(DIM / 32, DIM / 32), tb32>>>(Wo, Bhp, Blp, DIM, DIM);
    gemm_hmma_kernel<0><<<dim3(DIM / BN, ROWS_X / BM), 256, GEMM_SMEM>>>(
        Ahp, Alp, Bhp, Blp, out, nullptr, nullptr, ROWS_X, DIM);
}